// round 4
// baseline (speedup 1.0000x reference)
#include <cuda_runtime.h>
#include <cuda_bf16.h>
#include <math.h>

#define KG   256
#define DG   12
#define CG   9
#define HG   32
#define NIN  15
#define NEPS 1e-8f
#define LOG2E 1.4426950408889634f

// dynamic smem layout (float offsets)
#define OFF_G   0              // 256*12
#define OFF_F   3072           // 256*12
#define OFF_W1  6144           // 32*16
#define OFF_W2  6656           // 32*12
#define OFF_B1  7040           // 32
#define OFF_B2  7072           // 16
#define OFF_ST  7088           // two tiles of 256*36
#define TILE_FLOATS (256*36)
#define SMEM_FLOATS (OFF_ST + 2*TILE_FLOATS)

// epilogue helper: stage latent+sh, write coalesced, then normalize weights
__device__ __forceinline__ void epilogue(
    float* tile, int warp, int lane, int nwbase, int N,
    const float* lat, const float* shv, float invs,
    float* __restrict__ out_sh, float* __restrict__ out_latent,
    float* __restrict__ out_w)
{
    float* srow = tile + (warp*32 + lane) * 36;
    float4* sr4 = reinterpret_cast<float4*>(srow);
    sr4[0] = make_float4(lat[0], lat[1], lat[2],  lat[3]);
    sr4[1] = make_float4(lat[4], lat[5], lat[6],  lat[7]);
    sr4[2] = make_float4(lat[8], lat[9], lat[10], lat[11]);
    srow[12] = shv[0]; srow[13] = shv[1]; srow[14] = shv[2];
    srow[15] = shv[3]; srow[16] = shv[4]; srow[17] = shv[5];
    srow[18] = shv[6]; srow[19] = shv[7]; srow[20] = shv[8];
    __syncwarp();
    #pragma unroll
    for (int i = 0; i < 12; i++) {
        int e = i*32 + lane;
        int p = e / 12, d = e % 12;
        if (nwbase + p < N)
            out_latent[(size_t)nwbase * DG + e] = tile[(warp*32 + p)*36 + d];
    }
    #pragma unroll
    for (int i = 0; i < 9; i++) {
        int e = i*32 + lane;
        int p = e / 9, d = e % 9;
        if (nwbase + p < N)
            out_sh[(size_t)nwbase * CG + e] = tile[(warp*32 + p)*36 + 12 + d];
    }
    // coalesced in-place weight normalization
    #pragma unroll 2
    for (int p = 0; p < 32; p++) {
        float iv = __shfl_sync(0xffffffffu, invs, p);
        int np = nwbase + p;
        if (np < N) {
            float4* row = reinterpret_cast<float4*>(out_w + (size_t)np * KG);
            float4 a = row[lane];
            float4 b = row[lane + 32];
            a.x *= iv; a.y *= iv; a.z *= iv; a.w *= iv;
            b.x *= iv; b.y *= iv; b.z *= iv; b.w *= iv;
            row[lane] = a;
            row[lane + 32] = b;
        }
    }
}

__global__ __launch_bounds__(256, 2) void gpc_kernel(
    const float* __restrict__ probe,
    const float* __restrict__ mu,
    const float* __restrict__ log_s,
    const float* __restrict__ q,
    const float* __restrict__ F,
    const float* __restrict__ W1,
    const float* __restrict__ b1,
    const float* __restrict__ W2,
    const float* __restrict__ b2,
    float* __restrict__ out_sh,
    float* __restrict__ out_latent,
    float* __restrict__ out_w,
    int N)
{
    extern __shared__ float sm[];
    float* s_g   = sm + OFF_G;
    float* s_F   = sm + OFF_F;
    float* s_W1t = sm + OFF_W1;
    float* s_W2p = sm + OFF_W2;
    float* s_b1  = sm + OFF_B1;
    float* s_b2  = sm + OFF_B2;
    float* tile0 = sm + OFF_ST;
    float* tile1 = tile0 + TILE_FLOATS;

    const int t    = threadIdx.x;
    const int lane = t & 31;
    const int warp = t >> 5;

    // ---- per-gaussian precompute ----
    {
        const int k = t;
        float qw = q[k*4+0], qx = q[k*4+1], qy = q[k*4+2], qz = q[k*4+3];
        float inv = 1.0f / (sqrtf(qw*qw + qx*qx + qy*qy + qz*qz) + NEPS);
        qw *= inv; qx *= inv; qy *= inv; qz *= inv;

        float r00 = 1.f - 2.f*(qy*qy + qz*qz);
        float r01 = 2.f*(qx*qy - qw*qz);
        float r02 = 2.f*(qx*qz + qw*qy);
        float r10 = 2.f*(qx*qy + qw*qz);
        float r11 = 1.f - 2.f*(qx*qx + qz*qz);
        float r12 = 2.f*(qy*qz - qw*qx);
        float r20 = 2.f*(qx*qz - qw*qy);
        float r21 = 2.f*(qy*qz + qw*qx);
        float r22 = 1.f - 2.f*(qx*qx + qy*qy);

        float sx = expf(log_s[k*3+0]);
        float sy = expf(log_s[k*3+1]);
        float sz = expf(log_s[k*3+2]);
        float ix = 1.f / (sx*sx + NEPS);
        float iy = 1.f / (sy*sy + NEPS);
        float iz = 1.f / (sz*sz + NEPS);

        float p00 = r00*r00*ix + r01*r01*iy + r02*r02*iz;
        float p01 = r00*r10*ix + r01*r11*iy + r02*r12*iz;
        float p02 = r00*r20*ix + r01*r21*iy + r02*r22*iz;
        float p11 = r10*r10*ix + r11*r11*iy + r12*r12*iz;
        float p12 = r10*r20*ix + r11*r21*iy + r12*r22*iz;
        float p22 = r20*r20*ix + r21*r21*iy + r22*r22*iz;

        float smax = fmaxf(sx, fmaxf(sy, sz));
        float rad = 3.f * smax;

        const float sc = -0.5f * LOG2E;
        float4* g = reinterpret_cast<float4*>(s_g + k*12);
        g[0] = make_float4(p00*sc, 2.f*p01*sc, 2.f*p02*sc, p11*sc);
        g[1] = make_float4(2.f*p12*sc, p22*sc, mu[k*3+0], mu[k*3+1]);
        g[2] = make_float4(mu[k*3+2], rad*rad, 0.f, 0.f);
    }
    for (int i = t; i < KG*DG; i += 256) s_F[i] = F[i];
    for (int idx = t; idx < NIN*HG; idx += 256) {
        int i = idx / HG, j = idx % HG;
        s_W1t[j*16 + i] = W1[idx];
    }
    for (int idx = t; idx < HG*CG; idx += 256) {
        int j = idx / CG, c = idx % CG;
        s_W2p[j*12 + c] = W2[idx];
    }
    if (t < HG) { s_W1t[t*16 + 15] = 0.f; s_b1[t] = b1[t]; }
    if (t < HG*3) { int j = t / 3, c = 9 + t % 3; s_W2p[j*12 + c] = 0.f; }
    if (t < 16) s_b2[t] = (t < CG) ? b2[t] : 0.f;
    __syncthreads();

    // two probes per thread: n0 = base+t, n1 = base+256+t
    const int nbase   = blockIdx.x * 512;
    const int n0      = nbase + t;
    const int n1      = nbase + 256 + t;
    const int nwbase0 = nbase + warp * 32;
    const int nwbase1 = nbase + 256 + warp * 32;

    float px0 = 0.f, py0 = 0.f, pz0 = 0.f;
    float px1 = 0.f, py1 = 0.f, pz1 = 0.f;
    if (n0 < N) { px0 = probe[n0*3+0]; py0 = probe[n0*3+1]; pz0 = probe[n0*3+2]; }
    if (n1 < N) { px1 = probe[n1*3+0]; py1 = probe[n1*3+1]; pz1 = probe[n1*3+2]; }

    float* srow0 = tile0 + t * 36;
    float* srow1 = tile1 + t * 36;

    float lat0[DG], lat1[DG];
    #pragma unroll
    for (int d = 0; d < DG; d++) { lat0[d] = 0.f; lat1[d] = 0.f; }
    float sum0 = 0.f, sum1 = 0.f;

    const float4* g4 = reinterpret_cast<const float4*>(s_g);
    const float4* F4 = reinterpret_cast<const float4*>(s_F);

    // ---- pass 1: both probes share every parameter load ----
    for (int c = 0; c < KG; c += 32) {
        #pragma unroll 2
        for (int q4 = 0; q4 < 8; q4++) {
            float gv0[4], gv1[4];
            #pragma unroll
            for (int u = 0; u < 4; u++) {
                const int k = c + q4*4 + u;
                const float4 ga = g4[k*3+0];
                const float4 gb = g4[k*3+1];
                const float4 gc = g4[k*3+2];
                const float4 f0 = F4[k*3+0], f1 = F4[k*3+1], f2 = F4[k*3+2];

                // probe 0
                {
                    float dx = px0 - gb.z, dy = py0 - gb.w, dz = pz0 - gc.x;
                    float d2 = fmaf(dx, dx, fmaf(dy, dy, dz*dz));
                    float A  = fmaf(ga.x, dx, fmaf(ga.y, dy, ga.z*dz));
                    float B  = fmaf(ga.w, dy, gb.x*dz);
                    float arg = fmaf(dx, A, fmaf(dy, B, dz*(gb.y*dz)));
                    float e;
                    asm("ex2.approx.f32 %0, %1;" : "=f"(e) : "f"(arg));
                    float g = (d2 < gc.y) ? e : 0.f;
                    gv0[u] = g; sum0 += g;
                    lat0[0] += g*f0.x; lat0[1] += g*f0.y; lat0[2]  += g*f0.z; lat0[3]  += g*f0.w;
                    lat0[4] += g*f1.x; lat0[5] += g*f1.y; lat0[6]  += g*f1.z; lat0[7]  += g*f1.w;
                    lat0[8] += g*f2.x; lat0[9] += g*f2.y; lat0[10] += g*f2.z; lat0[11] += g*f2.w;
                }
                // probe 1
                {
                    float dx = px1 - gb.z, dy = py1 - gb.w, dz = pz1 - gc.x;
                    float d2 = fmaf(dx, dx, fmaf(dy, dy, dz*dz));
                    float A  = fmaf(ga.x, dx, fmaf(ga.y, dy, ga.z*dz));
                    float B  = fmaf(ga.w, dy, gb.x*dz);
                    float arg = fmaf(dx, A, fmaf(dy, B, dz*(gb.y*dz)));
                    float e;
                    asm("ex2.approx.f32 %0, %1;" : "=f"(e) : "f"(arg));
                    float g = (d2 < gc.y) ? e : 0.f;
                    gv1[u] = g; sum1 += g;
                    lat1[0] += g*f0.x; lat1[1] += g*f0.y; lat1[2]  += g*f0.z; lat1[3]  += g*f0.w;
                    lat1[4] += g*f1.x; lat1[5] += g*f1.y; lat1[6]  += g*f1.z; lat1[7]  += g*f1.w;
                    lat1[8] += g*f2.x; lat1[9] += g*f2.y; lat1[10] += g*f2.z; lat1[11] += g*f2.w;
                }
            }
            *reinterpret_cast<float4*>(srow0 + q4*4) = make_float4(gv0[0], gv0[1], gv0[2], gv0[3]);
            *reinterpret_cast<float4*>(srow1 + q4*4) = make_float4(gv1[0], gv1[1], gv1[2], gv1[3]);
        }
        __syncwarp();
        #pragma unroll 4
        for (int p = 0; p < 32; p++) {
            int np = nwbase0 + p;
            if (np < N)
                out_w[(size_t)np * KG + c + lane] = tile0[(warp*32 + p)*36 + lane];
        }
        #pragma unroll 4
        for (int p = 0; p < 32; p++) {
            int np = nwbase1 + p;
            if (np < N)
                out_w[(size_t)np * KG + c + lane] = tile1[(warp*32 + p)*36 + lane];
        }
        __syncwarp();
    }

    const float invs0 = 1.f / (sum0 + NEPS);
    const float invs1 = 1.f / (sum1 + NEPS);
    #pragma unroll
    for (int d = 0; d < DG; d++) { lat0[d] *= invs0; lat1[d] *= invs1; }

    // ---- MLP for both probes, sharing weight loads ----
    float sh0[12], sh1[12];
    #pragma unroll
    for (int c = 0; c < 12; c++) { sh0[c] = s_b2[c]; sh1[c] = s_b2[c]; }

    const float4* w1v = reinterpret_cast<const float4*>(s_W1t);
    const float4* w2v = reinterpret_cast<const float4*>(s_W2p);
    #pragma unroll
    for (int j = 0; j < HG; j++) {
        float4 w0 = w1v[j*4+0], w1 = w1v[j*4+1], w2 = w1v[j*4+2], w3 = w1v[j*4+3];
        float b = s_b1[j];
        float h0 = b
            + lat0[0]*w0.x + lat0[1]*w0.y + lat0[2]*w0.z  + lat0[3]*w0.w
            + lat0[4]*w1.x + lat0[5]*w1.y + lat0[6]*w1.z  + lat0[7]*w1.w
            + lat0[8]*w2.x + lat0[9]*w2.y + lat0[10]*w2.z + lat0[11]*w2.w
            + px0*w3.x + py0*w3.y + pz0*w3.z;
        float h1 = b
            + lat1[0]*w0.x + lat1[1]*w0.y + lat1[2]*w0.z  + lat1[3]*w0.w
            + lat1[4]*w1.x + lat1[5]*w1.y + lat1[6]*w1.z  + lat1[7]*w1.w
            + lat1[8]*w2.x + lat1[9]*w2.y + lat1[10]*w2.z + lat1[11]*w2.w
            + px1*w3.x + py1*w3.y + pz1*w3.z;
        h0 = fmaxf(h0, 0.f);
        h1 = fmaxf(h1, 0.f);
        float4 v0 = w2v[j*3+0], v1 = w2v[j*3+1], v2 = w2v[j*3+2];
        sh0[0] += h0*v0.x; sh0[1] += h0*v0.y; sh0[2]  += h0*v0.z; sh0[3]  += h0*v0.w;
        sh0[4] += h0*v1.x; sh0[5] += h0*v1.y; sh0[6]  += h0*v1.z; sh0[7]  += h0*v1.w;
        sh0[8] += h0*v2.x; sh0[9] += h0*v2.y; sh0[10] += h0*v2.z; sh0[11] += h0*v2.w;
        sh1[0] += h1*v0.x; sh1[1] += h1*v0.y; sh1[2]  += h1*v0.z; sh1[3]  += h1*v0.w;
        sh1[4] += h1*v1.x; sh1[5] += h1*v1.y; sh1[6]  += h1*v1.z; sh1[7]  += h1*v1.w;
        sh1[8] += h1*v2.x; sh1[9] += h1*v2.y; sh1[10] += h1*v2.z; sh1[11] += h1*v2.w;
    }

    __syncwarp();
    epilogue(tile0, warp, lane, nwbase0, N, lat0, sh0, invs0, out_sh, out_latent, out_w);
    __syncwarp();
    epilogue(tile1, warp, lane, nwbase1, N, lat1, sh1, invs1, out_sh, out_latent, out_w);
}

extern "C" void kernel_launch(void* const* d_in, const int* in_sizes, int n_in,
                              void* d_out, int out_size) {
    const float* probe = (const float*)d_in[0];
    const float* mu    = (const float*)d_in[1];
    const float* log_s = (const float*)d_in[2];
    const float* q     = (const float*)d_in[3];
    const float* F     = (const float*)d_in[4];
    const float* W1    = (const float*)d_in[5];
    const float* b1    = (const float*)d_in[6];
    const float* W2    = (const float*)d_in[7];
    const float* b2    = (const float*)d_in[8];

    const int N = in_sizes[0] / 3;

    float* out        = (float*)d_out;
    float* out_sh     = out;
    float* out_latent = out + (size_t)N * CG;
    float* out_w      = out_latent + (size_t)N * DG;

    const size_t smem_bytes = SMEM_FLOATS * sizeof(float);
    cudaFuncSetAttribute(gpc_kernel, cudaFuncAttributeMaxDynamicSharedMemorySize,
                         (int)smem_bytes);

    const int blocks = (N + 511) / 512;
    gpc_kernel<<<blocks, 256, smem_bytes>>>(probe, mu, log_s, q, F, W1, b1, W2, b2,
                                            out_sh, out_latent, out_w, N);
}

// round 5
// speedup vs baseline: 1.2051x; 1.2051x over previous
#include <cuda_runtime.h>
#include <cuda_bf16.h>
#include <math.h>

#define KG   256
#define DG   12
#define CG   9
#define HG   32
#define NIN  15
#define NEPS 1e-8f
#define LOG2E 1.4426950408889634f

// dynamic smem layout (float offsets)
#define OFF_G   0              // 256*12  packed gaussian params
#define OFF_F   3072           // 256*12
#define OFF_W1  6144           // 32*16   W1 transposed+padded
#define OFF_W2  6656           // 32*12   W2 padded
#define OFF_B1  7040           // 32
#define OFF_B2  7072           // 16 (12 used)
#define OFF_ST  7088           // 256*36  staging tile
#define SMEM_FLOATS (OFF_ST + 256*36)

struct alignas(16) Q2 { unsigned long long lo, hi; };   // one float4 as 2 f32x2 packs

__device__ __forceinline__ void ffma2(unsigned long long& acc,
                                      unsigned long long ab,
                                      unsigned long long cd) {
    asm("fma.rn.f32x2 %0, %1, %2, %0;" : "+l"(acc) : "l"(ab), "l"(cd));
}

__global__ __launch_bounds__(256, 3) void gpc_kernel(
    const float* __restrict__ probe,
    const float* __restrict__ mu,
    const float* __restrict__ log_s,
    const float* __restrict__ q,
    const float* __restrict__ F,
    const float* __restrict__ W1,
    const float* __restrict__ b1,
    const float* __restrict__ W2,
    const float* __restrict__ b2,
    float* __restrict__ out_sh,        // [N,C]
    float* __restrict__ out_latent,    // [N,D]
    float* __restrict__ out_w,         // [N,K]
    int N)
{
    extern __shared__ float sm[];
    float* s_g   = sm + OFF_G;
    float* s_F   = sm + OFF_F;
    float* s_W1t = sm + OFF_W1;
    float* s_W2p = sm + OFF_W2;
    float* s_b1  = sm + OFF_B1;
    float* s_b2  = sm + OFF_B2;
    float* s_st  = sm + OFF_ST;

    const int t    = threadIdx.x;
    const int lane = t & 31;
    const int warp = t >> 5;

    // ---- per-gaussian precompute: thread t = gaussian t ----
    {
        const int k = t;
        float qw = q[k*4+0], qx = q[k*4+1], qy = q[k*4+2], qz = q[k*4+3];
        float inv = 1.0f / (sqrtf(qw*qw + qx*qx + qy*qy + qz*qz) + NEPS);
        qw *= inv; qx *= inv; qy *= inv; qz *= inv;

        float r00 = 1.f - 2.f*(qy*qy + qz*qz);
        float r01 = 2.f*(qx*qy - qw*qz);
        float r02 = 2.f*(qx*qz + qw*qy);
        float r10 = 2.f*(qx*qy + qw*qz);
        float r11 = 1.f - 2.f*(qx*qx + qz*qz);
        float r12 = 2.f*(qy*qz - qw*qx);
        float r20 = 2.f*(qx*qz - qw*qy);
        float r21 = 2.f*(qy*qz + qw*qx);
        float r22 = 1.f - 2.f*(qx*qx + qy*qy);

        float sx = expf(log_s[k*3+0]);
        float sy = expf(log_s[k*3+1]);
        float sz = expf(log_s[k*3+2]);
        float ix = 1.f / (sx*sx + NEPS);
        float iy = 1.f / (sy*sy + NEPS);
        float iz = 1.f / (sz*sz + NEPS);

        float p00 = r00*r00*ix + r01*r01*iy + r02*r02*iz;
        float p01 = r00*r10*ix + r01*r11*iy + r02*r12*iz;
        float p02 = r00*r20*ix + r01*r21*iy + r02*r22*iz;
        float p11 = r10*r10*ix + r11*r11*iy + r12*r12*iz;
        float p12 = r10*r20*ix + r11*r21*iy + r12*r22*iz;
        float p22 = r20*r20*ix + r21*r21*iy + r22*r22*iz;

        float smax = fmaxf(sx, fmaxf(sy, sz));
        float rad = 3.f * smax;

        const float sc = -0.5f * LOG2E;   // exp(-0.5 m) = exp2(sc * m)
        float4* g = reinterpret_cast<float4*>(s_g + k*12);
        g[0] = make_float4(p00*sc, 2.f*p01*sc, 2.f*p02*sc, p11*sc);
        g[1] = make_float4(2.f*p12*sc, p22*sc, mu[k*3+0], mu[k*3+1]);
        g[2] = make_float4(mu[k*3+2], rad*rad, 0.f, 0.f);
    }
    for (int i = t; i < KG*DG; i += 256) s_F[i] = F[i];
    for (int idx = t; idx < NIN*HG; idx += 256) {
        int i = idx / HG, j = idx % HG;
        s_W1t[j*16 + i] = W1[idx];
    }
    for (int idx = t; idx < HG*CG; idx += 256) {
        int j = idx / CG, c = idx % CG;
        s_W2p[j*12 + c] = W2[idx];
    }
    if (t < HG) { s_W1t[t*16 + 15] = 0.f; s_b1[t] = b1[t]; }
    if (t < HG*3) { int j = t / 3, c = 9 + t % 3; s_W2p[j*12 + c] = 0.f; }
    if (t < 16) s_b2[t] = (t < CG) ? b2[t] : 0.f;
    __syncthreads();

    const int nbase  = blockIdx.x * 256;
    const int n      = nbase + t;
    const int nwbase = nbase + warp * 32;
    const bool valid = (n < N);

    float px = 0.f, py = 0.f, pz = 0.f;
    if (valid) { px = probe[n*3+0]; py = probe[n*3+1]; pz = probe[n*3+2]; }

    float* srow = s_st + t * 36;

    // latent accumulators as six f32x2 packs
    unsigned long long l01 = 0ull, l23 = 0ull, l45 = 0ull,
                       l67 = 0ull, l89 = 0ull, lAB = 0ull;
    float sum = 0.f;

    const float4* g4 = reinterpret_cast<const float4*>(s_g);
    const Q2*     Fq = reinterpret_cast<const Q2*>(s_F);   // 3 Q2 per gaussian row

    const int p_off = lane >> 3;   // 0..3  (probe within quad)
    const int qidx  = lane & 7;    // 0..7  (float4 index within 32-float row)

    // ---- pass 1: gvals (unnormalized) + latent; coalesced staging writes ----
    for (int c = 0; c < KG; c += 32) {
        #pragma unroll
        for (int q4 = 0; q4 < 8; q4++) {
            float gv[4];
            #pragma unroll
            for (int u = 0; u < 4; u++) {
                const int k = c + q4*4 + u;
                const float4 ga = g4[k*3+0];
                const float4 gb = g4[k*3+1];
                const float4 gc = g4[k*3+2];
                float dx = px - gb.z, dy = py - gb.w, dz = pz - gc.x;
                float d2 = fmaf(dx, dx, fmaf(dy, dy, dz*dz));
                float A  = fmaf(ga.x, dx, fmaf(ga.y, dy, ga.z*dz));
                float B  = fmaf(ga.w, dy, gb.x*dz);
                float arg = fmaf(dx, A, fmaf(dy, B, dz*(gb.y*dz)));
                float e;
                asm("ex2.approx.f32 %0, %1;" : "=f"(e) : "f"(arg));
                float g = (d2 < gc.y) ? e : 0.f;
                gv[u] = g;
                sum += g;

                unsigned long long gg;
                asm("mov.b64 %0, {%1, %1};" : "=l"(gg) : "f"(g));
                const Q2 fA = Fq[k*3+0];
                const Q2 fB = Fq[k*3+1];
                const Q2 fC = Fq[k*3+2];
                ffma2(l01, gg, fA.lo); ffma2(l23, gg, fA.hi);
                ffma2(l45, gg, fB.lo); ffma2(l67, gg, fB.hi);
                ffma2(l89, gg, fC.lo); ffma2(lAB, gg, fC.hi);
            }
            *reinterpret_cast<float4*>(srow + q4*4) = make_float4(gv[0], gv[1], gv[2], gv[3]);
        }
        __syncwarp();
        // warp writes 32 probes' 32-float segments; 4 probes per STG.128
        #pragma unroll
        for (int pb = 0; pb < 32; pb += 4) {
            int p  = pb + p_off;
            int np = nwbase + p;
            if (np < N) {
                float4 v = *reinterpret_cast<const float4*>(&s_st[(warp*32 + p)*36 + qidx*4]);
                *reinterpret_cast<float4*>(&out_w[(size_t)np * KG + c + qidx*4]) = v;
            }
        }
        __syncwarp();
    }

    const float invs = 1.f / (sum + NEPS);

    float lat[DG];
    {
        float2 u;
        u = *reinterpret_cast<float2*>(&l01); lat[0]  = u.x*invs; lat[1]  = u.y*invs;
        u = *reinterpret_cast<float2*>(&l23); lat[2]  = u.x*invs; lat[3]  = u.y*invs;
        u = *reinterpret_cast<float2*>(&l45); lat[4]  = u.x*invs; lat[5]  = u.y*invs;
        u = *reinterpret_cast<float2*>(&l67); lat[6]  = u.x*invs; lat[7]  = u.y*invs;
        u = *reinterpret_cast<float2*>(&l89); lat[8]  = u.x*invs; lat[9]  = u.y*invs;
        u = *reinterpret_cast<float2*>(&lAB); lat[10] = u.x*invs; lat[11] = u.y*invs;
    }

    // ---- MLP: [latent, pos, pad](16) @ W1t -> relu -> @ W2p ----
    float sh[12];
    #pragma unroll
    for (int c = 0; c < 12; c++) sh[c] = s_b2[c];

    const float4* w1v = reinterpret_cast<const float4*>(s_W1t);
    const float4* w2v = reinterpret_cast<const float4*>(s_W2p);
    #pragma unroll
    for (int j = 0; j < HG; j++) {
        float4 w0 = w1v[j*4+0], w1 = w1v[j*4+1], w2 = w1v[j*4+2], w3 = w1v[j*4+3];
        float h = s_b1[j]
            + lat[0]*w0.x + lat[1]*w0.y + lat[2]*w0.z  + lat[3]*w0.w
            + lat[4]*w1.x + lat[5]*w1.y + lat[6]*w1.z  + lat[7]*w1.w
            + lat[8]*w2.x + lat[9]*w2.y + lat[10]*w2.z + lat[11]*w2.w
            + px*w3.x + py*w3.y + pz*w3.z;
        h = fmaxf(h, 0.f);
        float4 v0 = w2v[j*3+0], v1 = w2v[j*3+1], v2 = w2v[j*3+2];
        sh[0] += h*v0.x; sh[1] += h*v0.y; sh[2]  += h*v0.z; sh[3]  += h*v0.w;
        sh[4] += h*v1.x; sh[5] += h*v1.y; sh[6]  += h*v1.z; sh[7]  += h*v1.w;
        sh[8] += h*v2.x; sh[9] += h*v2.y; sh[10] += h*v2.z; sh[11] += h*v2.w;
    }

    // ---- stage latent (12) + sh (9) -> coalesced output writes ----
    {
        float4* sr4 = reinterpret_cast<float4*>(srow);
        sr4[0] = make_float4(lat[0], lat[1], lat[2],  lat[3]);
        sr4[1] = make_float4(lat[4], lat[5], lat[6],  lat[7]);
        sr4[2] = make_float4(lat[8], lat[9], lat[10], lat[11]);
        srow[12] = sh[0]; srow[13] = sh[1]; srow[14] = sh[2];
        srow[15] = sh[3]; srow[16] = sh[4]; srow[17] = sh[5];
        srow[18] = sh[6]; srow[19] = sh[7]; srow[20] = sh[8];
    }
    __syncwarp();
    #pragma unroll
    for (int i = 0; i < 12; i++) {
        int e = i*32 + lane;
        int p = e / 12, d = e % 12;
        if (nwbase + p < N)
            out_latent[(size_t)nwbase * DG + e] = s_st[(warp*32 + p)*36 + d];
    }
    #pragma unroll
    for (int i = 0; i < 9; i++) {
        int e = i*32 + lane;
        int p = e / 9, d = e % 9;
        if (nwbase + p < N)
            out_sh[(size_t)nwbase * CG + e] = s_st[(warp*32 + p)*36 + 12 + d];
    }

    // ---- pass 2: coalesced in-place weight normalization ----
    #pragma unroll 2
    for (int p = 0; p < 32; p++) {
        float iv = __shfl_sync(0xffffffffu, invs, p);
        int np = nwbase + p;
        if (np < N) {
            float4* row = reinterpret_cast<float4*>(out_w + (size_t)np * KG);
            float4 a = row[lane];
            float4 b = row[lane + 32];
            a.x *= iv; a.y *= iv; a.z *= iv; a.w *= iv;
            b.x *= iv; b.y *= iv; b.z *= iv; b.w *= iv;
            row[lane] = a;
            row[lane + 32] = b;
        }
    }
}

extern "C" void kernel_launch(void* const* d_in, const int* in_sizes, int n_in,
                              void* d_out, int out_size) {
    const float* probe = (const float*)d_in[0];
    const float* mu    = (const float*)d_in[1];
    const float* log_s = (const float*)d_in[2];
    const float* q     = (const float*)d_in[3];
    const float* F     = (const float*)d_in[4];
    const float* W1    = (const float*)d_in[5];
    const float* b1    = (const float*)d_in[6];
    const float* W2    = (const float*)d_in[7];
    const float* b2    = (const float*)d_in[8];

    const int N = in_sizes[0] / 3;

    float* out        = (float*)d_out;
    float* out_sh     = out;
    float* out_latent = out + (size_t)N * CG;
    float* out_w      = out_latent + (size_t)N * DG;

    const size_t smem_bytes = SMEM_FLOATS * sizeof(float);
    cudaFuncSetAttribute(gpc_kernel, cudaFuncAttributeMaxDynamicSharedMemorySize,
                         (int)smem_bytes);

    const int blocks = (N + 255) / 256;
    gpc_kernel<<<blocks, 256, smem_bytes>>>(probe, mu, log_s, q, F, W1, b1, W2, b2,
                                            out_sh, out_latent, out_w, N);
}